// round 11
// baseline (speedup 1.0000x reference)
#include <cuda_runtime.h>
#include <cuda_fp16.h>
#include <math_constants.h>
#include <cstdint>

#define Q_LEN 2048
#define HIST  2048
#define KLEN  4096
#define NH    12
#define KVH   2
#define DH    128
#define HID   1536
#define KVDIM 256
#define GROUPS 6
#define NITEMS (NH * 16)

// Scratch (device globals, allocation-free)
__device__ __align__(16) __half g_q[Q_LEN * HID];      // [t][h*128+d]
__device__ __align__(16) __half g_k[KLEN * KVDIM];     // [key][kvh*128+d]
__device__ __align__(16) __half g_v[KVDIM * KLEN];     // TRANSPOSED [kvh*128+d][key]
__device__ __align__(16) __half g_att[Q_LEN * HID];    // [t][h*128+d]
__device__ __align__(16) __half g_x[Q_LEN * HID];      // [t][k]
__device__ __align__(16) __half g_wq[HID * HID];       // TRANSPOSED [n][k]
__device__ __align__(16) __half g_wk[KVDIM * HID];     // TRANSPOSED [n][k]
__device__ __align__(16) __half g_wv[KVDIM * HID];     // TRANSPOSED [n][k]
__device__ __align__(16) __half g_wo[HID * HID];       // TRANSPOSED [n][k]
__device__ unsigned int g_work;

// ---------------------------------------------------------------------------
// helpers
// ---------------------------------------------------------------------------
__device__ __forceinline__ uint32_t h2pack(float a, float b) {
    __half2 h = __floats2half2_rn(a, b);
    return *(uint32_t*)&h;
}

__device__ __forceinline__ void mma_f16(float d[4], const uint32_t a[4],
                                        const uint32_t b[2]) {
    asm volatile(
        "mma.sync.aligned.m16n8k16.row.col.f32.f16.f16.f32 "
        "{%0,%1,%2,%3}, {%4,%5,%6,%7}, {%8,%9}, {%0,%1,%2,%3};\n"
        : "+f"(d[0]), "+f"(d[1]), "+f"(d[2]), "+f"(d[3])
        : "r"(a[0]), "r"(a[1]), "r"(a[2]), "r"(a[3]), "r"(b[0]), "r"(b[1]));
}

__device__ __forceinline__ void cpa16(__half* dst, const __half* src) {
    uint32_t d = (uint32_t)__cvta_generic_to_shared(dst);
    asm volatile("cp.async.cg.shared.global [%0], [%1], 16;\n"
                 :: "r"(d), "l"(src));
}
#define CP_COMMIT() asm volatile("cp.async.commit_group;\n")
#define CP_WAIT(n)  asm volatile("cp.async.wait_group %0;\n" :: "n"(n))

// ---------------------------------------------------------------------------
// cvt: plain fp32 -> fp16 (x, k_hist); reset work counter
// ---------------------------------------------------------------------------
__global__ __launch_bounds__(256) void cvt_kernel(
    const float* __restrict__ x, const float* __restrict__ kh)
{
    if (blockIdx.x == 0 && threadIdx.x == 0) g_work = 0u;
    const int SX  = Q_LEN * HID / 2;
    const int SKH = HIST * KVDIM / 2;
    int stride = gridDim.x * blockDim.x;
    for (int i = blockIdx.x * blockDim.x + threadIdx.x; i < SX + SKH;
         i += stride) {
        if (i < SX) {
            float2 v = ((const float2*)x)[i];
            ((uint32_t*)g_x)[i] = h2pack(v.x, v.y);
        } else {
            int j = i - SX;
            float2 v = ((const float2*)kh)[j];
            ((uint32_t*)g_k)[j] = h2pack(v.x, v.y);
        }
    }
}

// ---------------------------------------------------------------------------
// Tiled transpose fp32->fp16 (coalesced both sides): weights and v_hist.
// 32x32 tiles, 256 threads. Tile jobs packed into blockIdx.x.
//  [0,2304)      Wq   [1536k][1536n] -> g_wq[n][k]
//  [2304,2688)   Wk   [1536][256]    -> g_wk[n][k]
//  [2688,3072)   Wv   [1536][256]    -> g_wv[n][k]
//  [3072,5376)   Wo   [1536][1536]   -> g_wo[n][k]
//  [5376,5888)   v_hist [2048][256]  -> g_v[col][key] (row len KLEN)
// ---------------------------------------------------------------------------
__global__ __launch_bounds__(256) void trans_kernel(
    const float* __restrict__ wq, const float* __restrict__ wk,
    const float* __restrict__ wv, const float* __restrict__ wo,
    const float* __restrict__ vh)
{
    __shared__ float tile[32][33];
    int b = blockIdx.x;
    const float* src; __half* dst;
    int inCols; size_t outStride; int tb;
    if (b < 2304)      { src = wq; dst = g_wq; inCols = 1536; outStride = 1536; tb = b; }
    else if (b < 2688) { src = wk; dst = g_wk; inCols = 256;  outStride = 1536; tb = b - 2304; }
    else if (b < 3072) { src = wv; dst = g_wv; inCols = 256;  outStride = 1536; tb = b - 2688; }
    else if (b < 5376) { src = wo; dst = g_wo; inCols = 1536; outStride = 1536; tb = b - 3072; }
    else               { src = vh; dst = g_v;  inCols = 256;  outStride = KLEN; tb = b - 5376; }
    int tilesPerRow = inCols >> 5;
    int row0 = (tb / tilesPerRow) << 5;
    int col0 = (tb % tilesPerRow) << 5;
    int tx = threadIdx.x & 31, ty = threadIdx.x >> 5;
#pragma unroll
    for (int l = 0; l < 4; l++) {
        int r = ty + 8 * l;
        tile[r][tx] = src[(size_t)(row0 + r) * inCols + col0 + tx];
    }
    __syncthreads();
#pragma unroll
    for (int l = 0; l < 4; l++) {
        int r = ty + 8 * l;   // output row = input col
        dst[(size_t)(col0 + r) * outStride + row0 + tx] =
            __float2half_rn(tile[tx][r]);
    }
}

// ---------------------------------------------------------------------------
// fp16 GEMM, cp.async 2-stage. C[128,128] = A[M,K] @ Bt[n][k] (+bias)
// modes: 0 = fp32 out, 1 = fp16 plain out, 2 = fp16 V-transposed out
// ---------------------------------------------------------------------------
#define LDA_G 40
#define LDB_G 40
#define GEMM_SMEM ((2 * 128 * LDA_G + 2 * 128 * LDB_G) * 2)

__device__ __forceinline__ void gemm_body_h(
    const __half* __restrict__ A, const __half* __restrict__ Bt,
    const float* __restrict__ bias, void* __restrict__ Cv,
    int row0, int col0, int K, int ldc, int mode)
{
    extern __shared__ __half smg[];
    __half* As = smg;
    __half* Bs = smg + 2 * 128 * LDA_G;

    const int tid  = threadIdx.x;
    const int w    = tid >> 5;
    const int lane = tid & 31;
    const int g    = lane >> 2;
    const int t    = lane & 3;
    const int wm   = w >> 2;
    const int wn   = w & 3;

    float acc[16][4];
#pragma unroll
    for (int i = 0; i < 16; i++)
#pragma unroll
        for (int j = 0; j < 4; j++) acc[i][j] = 0.f;

    auto load_stage = [&](int s, int k0) {
#pragma unroll
        for (int l = 0; l < 2; l++) {
            int i = tid + l * 256;
            int r = i >> 2, c = (i & 3) << 3;
            cpa16(As + (s * 128 + r) * LDA_G + c,
                  A + (size_t)(row0 + r) * K + k0 + c);
        }
#pragma unroll
        for (int l = 0; l < 2; l++) {
            int i = tid + l * 256;
            int r = i >> 2, c = (i & 3) << 3;
            cpa16(Bs + (s * 128 + r) * LDB_G + c,
                  Bt + (size_t)(col0 + r) * K + k0 + c);
        }
        CP_COMMIT();
    };

    load_stage(0, 0);
    const int KT = K / 32;
    for (int kt = 0; kt < KT; kt++) {
        if (kt + 1 < KT) { load_stage((kt + 1) & 1, (kt + 1) * 32); CP_WAIT(1); }
        else             { CP_WAIT(0); }
        __syncthreads();
        const __half* Ab = As + (kt & 1) * 128 * LDA_G;
        const __half* Bb = Bs + (kt & 1) * 128 * LDB_G;
#pragma unroll
        for (int k16 = 0; k16 < 32; k16 += 16) {
            uint32_t a[4][4];
#pragma unroll
            for (int mi = 0; mi < 4; mi++) {
                const __half* ab = Ab + (wm * 64 + mi * 16 + g) * LDA_G + k16;
                a[mi][0] = *(const uint32_t*)(ab + 2 * t);
                a[mi][1] = *(const uint32_t*)(ab + 8 * LDA_G + 2 * t);
                a[mi][2] = *(const uint32_t*)(ab + 2 * t + 8);
                a[mi][3] = *(const uint32_t*)(ab + 8 * LDA_G + 2 * t + 8);
            }
#pragma unroll
            for (int ni = 0; ni < 4; ni++) {
                const __half* bp = Bb + (wn * 32 + ni * 8 + g) * LDB_G + k16;
                uint32_t b[2];
                b[0] = *(const uint32_t*)(bp + 2 * t);
                b[1] = *(const uint32_t*)(bp + 2 * t + 8);
#pragma unroll
                for (int mi = 0; mi < 4; mi++)
                    mma_f16(acc[mi * 4 + ni], a[mi], b);
            }
        }
        __syncthreads();
    }

#pragma unroll
    for (int mi = 0; mi < 4; mi++)
#pragma unroll
        for (int ni = 0; ni < 4; ni++) {
            int col = col0 + wn * 32 + ni * 8 + 2 * t;
            float b0 = bias ? bias[col]     : 0.f;
            float b1 = bias ? bias[col + 1] : 0.f;
            int r0 = row0 + wm * 64 + mi * 16 + g;
            float v00 = acc[mi * 4 + ni][0] + b0;
            float v01 = acc[mi * 4 + ni][1] + b1;
            float v10 = acc[mi * 4 + ni][2] + b0;
            float v11 = acc[mi * 4 + ni][3] + b1;
            if (mode == 0) {
                float* C = (float*)Cv;
                *(float2*)(C + (size_t)r0 * ldc + col)       = make_float2(v00, v01);
                *(float2*)(C + (size_t)(r0 + 8) * ldc + col) = make_float2(v10, v11);
            } else if (mode == 1) {
                __half* C = (__half*)Cv;
                *(uint32_t*)(C + (size_t)r0 * ldc + col)       = h2pack(v00, v01);
                *(uint32_t*)(C + (size_t)(r0 + 8) * ldc + col) = h2pack(v10, v11);
            } else {
                __half* C = (__half*)Cv;
                int key = HIST + r0;
                C[(size_t)col * KLEN + key]           = __float2half_rn(v00);
                C[(size_t)(col + 1) * KLEN + key]     = __float2half_rn(v01);
                C[(size_t)col * KLEN + key + 8]       = __float2half_rn(v10);
                C[(size_t)(col + 1) * KLEN + key + 8] = __float2half_rn(v11);
            }
        }
}

// grid.x: 0..11 -> Wq, 12..13 -> Wk, 14..15 -> Wv
__global__ __launch_bounds__(256) void gemm_qkv_kernel(
    const float* __restrict__ bq, const float* __restrict__ bk,
    const float* __restrict__ bv)
{
    int bx   = blockIdx.x;
    int row0 = blockIdx.y * 128;
    if (bx < 12) {
        gemm_body_h(g_x, g_wq, bq, g_q, row0, bx * 128, HID, HID, 1);
    } else if (bx < 14) {
        gemm_body_h(g_x, g_wk, bk, g_k + (size_t)HIST * KVDIM, row0,
                    (bx - 12) * 128, HID, KVDIM, 1);
    } else {
        gemm_body_h(g_x, g_wv, bv, g_v, row0, (bx - 14) * 128, HID, 0, 2);
    }
}

__global__ __launch_bounds__(256) void gemm_wo_kernel(float* __restrict__ out)
{
    gemm_body_h(g_att, g_wo, nullptr, out, blockIdx.y * 128,
                blockIdx.x * 128, HID, HID, 0);
}

// ---------------------------------------------------------------------------
// RoPE in fp16 (compute fp32)
// ---------------------------------------------------------------------------
__global__ __launch_bounds__(64) void rope_kernel(
    const float* __restrict__ fcos, const float* __restrict__ fsin)
{
    int b  = blockIdx.x;
    int t  = b / 14;
    int hh = b % 14;
    int d  = threadIdx.x;
    float c = fcos[t * 64 + d];
    float s = fsin[t * 64 + d];
    __half* base;
    if (hh < 12) base = g_q + (size_t)t * HID + hh * DH;
    else         base = g_k + (size_t)(HIST + t) * KVDIM + (hh - 12) * DH;
    float x1 = __half2float(base[d]);
    float x2 = __half2float(base[d + 64]);
    base[d]      = __float2half_rn(x1 * c - x2 * s);
    base[d + 64] = __float2half_rn(x1 * s + x2 * c);
}

// ---------------------------------------------------------------------------
// Persistent flash attention, fp16 mma, KTILE=128, one barrier per tile,
// K+V double-buffered, S/softmax/PV in two 64-key halves (no reg spills).
// ---------------------------------------------------------------------------
#define KTILE 128
#define LDQ 136   // halves
#define LDK 136
#define LDVT 136
#define LDP 72
#define AQ_H (128 * LDQ)
#define AK_H (2 * 128 * LDK)
#define AV_H (2 * 128 * LDVT)
#define AP_H (8 * 16 * LDP)
#define AW_H (AQ_H + AK_H + AV_H + AP_H)
#define ATTN_SMEM (AW_H * 2 + 16)

__global__ __launch_bounds__(256) void attn_kernel()
{
    extern __shared__ __half smh[];
    __half* Qs = smh;
    __half* Ks = smh + AQ_H;
    __half* Vs = smh + AQ_H + AK_H;
    __half* Ps = smh + AQ_H + AK_H + AV_H;
    int* widx = (int*)(smh + AW_H);

    const int tid  = threadIdx.x;
    const int w    = tid >> 5;
    const int lane = tid & 31;
    const int g    = lane >> 2;
    const int t    = lane & 3;
    const float SC = 0.12751689932560563f;  // 1/sqrt(128) * log2(e)

    for (;;) {
        if (tid == 0) *widx = (int)atomicAdd(&g_work, 1u);
        __syncthreads();
        const int item = *widx;
        if (item >= NITEMS) break;
        const int qt   = 15 - item / NH;     // descending nkt (LPT)
        const int head = item % NH;
        const int q0   = qt * 128;
        const int kvh  = head / GROUPS;

        // Q tile (128 x 128 halves)
#pragma unroll
        for (int l = 0; l < 8; l++) {
            int i = tid + l * 256;
            int r = i >> 4, c = (i & 15) << 3;
            cpa16(Qs + r * LDQ + c, g_q + (size_t)(q0 + r) * HID + head * DH + c);
        }
        // K(0), V(0) into stage 0
#pragma unroll
        for (int l = 0; l < 8; l++) {
            int i = tid + l * 256;
            int r = i >> 4, c = (i & 15) << 3;
            cpa16(Ks + r * LDK + c, g_k + (size_t)r * KVDIM + kvh * DH + c);
        }
#pragma unroll
        for (int l = 0; l < 8; l++) {
            int i = tid + l * 256;
            int r = i >> 4, c = (i & 15) << 3;
            cpa16(Vs + r * LDVT + c, g_v + (size_t)(kvh * DH + r) * KLEN + c);
        }
        CP_COMMIT();
        CP_WAIT(0);
        __syncthreads();

        // capture Q fragments
        uint32_t qf[8][4];
#pragma unroll
        for (int k16 = 0; k16 < 8; k16++) {
            const __half* qb = Qs + (w * 16 + g) * LDQ + k16 * 16;
            qf[k16][0] = *(const uint32_t*)(qb + 2 * t);
            qf[k16][1] = *(const uint32_t*)(qb + 8 * LDQ + 2 * t);
            qf[k16][2] = *(const uint32_t*)(qb + 2 * t + 8);
            qf[k16][3] = *(const uint32_t*)(qb + 8 * LDQ + 2 * t + 8);
        }

        float o[16][4];
#pragma unroll
        for (int i = 0; i < 16; i++)
#pragma unroll
            for (int j = 0; j < 4; j++) o[i][j] = 0.f;
        float m0 = -1e30f, m1 = -1e30f, l0 = 0.f, l1 = 0.f;
        const int row0g = q0 + w * 16 + g;
        const int nkt = qt + 17;             // (q0 + 128 + HIST) / KTILE

        for (int kt = 0; kt < nkt; kt++) {
            const int kb = kt * KTILE;
            if (kt > 0) {
                CP_WAIT(0);          // K(kt), V(kt) arrived
                __syncthreads();     // ...and tile kt-1 fully consumed
            }
            // prefetch K(kt+1), V(kt+1)
            if (kt + 1 < nkt) {
                __half* Knx = Ks + ((kt + 1) & 1) * 128 * LDK;
                __half* Vnx = Vs + ((kt + 1) & 1) * 128 * LDVT;
#pragma unroll
                for (int l = 0; l < 8; l++) {
                    int i = tid + l * 256;
                    int r = i >> 4, c = (i & 15) << 3;
                    cpa16(Knx + r * LDK + c,
                          g_k + (size_t)(kb + KTILE + r) * KVDIM + kvh * DH + c);
                }
#pragma unroll
                for (int l = 0; l < 8; l++) {
                    int i = tid + l * 256;
                    int r = i >> 4, c = (i & 15) << 3;
                    cpa16(Vnx + r * LDVT + c,
                          g_v + (size_t)(kvh * DH + r) * KLEN + kb + KTILE + c);
                }
                CP_COMMIT();
            }

            const __half* Kcur = Ks + (kt & 1) * 128 * LDK;
            const __half* Vcur = Vs + (kt & 1) * 128 * LDVT;
            const bool maskTile = (kt == nkt - 1);

            // two 64-key halves (keeps regs below spill threshold)
#pragma unroll
            for (int h = 0; h < 2; h++) {
                const __half* Kh = Kcur + h * 64 * LDK;

                // S = Q K^T : 16 rows x 64 keys
                float s[8][4];
#pragma unroll
                for (int j = 0; j < 8; j++)
#pragma unroll
                    for (int e = 0; e < 4; e++) s[j][e] = 0.f;
#pragma unroll
                for (int k16 = 0; k16 < 8; k16++) {
#pragma unroll
                    for (int j = 0; j < 8; j++) {
                        const __half* kp = Kh + (j * 8 + g) * LDK + k16 * 16;
                        uint32_t b[2];
                        b[0] = *(const uint32_t*)(kp + 2 * t);
                        b[1] = *(const uint32_t*)(kp + 2 * t + 8);
                        mma_f16(s[j], qf[k16], b);
                    }
                }

                // scale + causal mask (only final tile is partial)
                if (maskTile) {
#pragma unroll
                    for (int j = 0; j < 8; j++) {
                        int colg = kb + h * 64 + j * 8 + 2 * t;
                        s[j][0] = (colg     <= row0g + HIST)     ? s[j][0] * SC : -1e30f;
                        s[j][1] = (colg + 1 <= row0g + HIST)     ? s[j][1] * SC : -1e30f;
                        s[j][2] = (colg     <= row0g + 8 + HIST) ? s[j][2] * SC : -1e30f;
                        s[j][3] = (colg + 1 <= row0g + 8 + HIST) ? s[j][3] * SC : -1e30f;
                    }
                } else {
#pragma unroll
                    for (int j = 0; j < 8; j++) {
                        s[j][0] *= SC; s[j][1] *= SC;
                        s[j][2] *= SC; s[j][3] *= SC;
                    }
                }

                // online softmax (quad reduce)
                float mx0 = -1e30f, mx1 = -1e30f;
#pragma unroll
                for (int j = 0; j < 8; j++) {
                    mx0 = fmaxf(mx0, fmaxf(s[j][0], s[j][1]));
                    mx1 = fmaxf(mx1, fmaxf(s[j][2], s[j][3]));
                }
                mx0 = fmaxf(mx0, __shfl_xor_sync(0xffffffffu, mx0, 1));
                mx0 = fmaxf(mx0, __shfl_xor_sync(0xffffffffu, mx0, 2));
                mx1 = fmaxf(mx1, __shfl_xor_sync(0xffffffffu, mx1, 1));
                mx1 = fmaxf(mx1, __shfl_xor_sync(0xffffffffu, mx1, 2));
                float mn0 = fmaxf(m0, mx0), mn1 = fmaxf(m1, mx1);
                float c0 = exp2f(m0 - mn0), c1 = exp2f(m1 - mn1);
                m0 = mn0; m1 = mn1;
                float sum0 = 0.f, sum1 = 0.f;
#pragma unroll
                for (int j = 0; j < 8; j++) {
                    s[j][0] = exp2f(s[j][0] - m0);
                    s[j][1] = exp2f(s[j][1] - m0);
                    s[j][2] = exp2f(s[j][2] - m1);
                    s[j][3] = exp2f(s[j][3] - m1);
                    sum0 += s[j][0] + s[j][1];
                    sum1 += s[j][2] + s[j][3];
                }
                sum0 += __shfl_xor_sync(0xffffffffu, sum0, 1);
                sum0 += __shfl_xor_sync(0xffffffffu, sum0, 2);
                sum1 += __shfl_xor_sync(0xffffffffu, sum1, 1);
                sum1 += __shfl_xor_sync(0xffffffffu, sum1, 2);
                l0 = l0 * c0 + sum0;
                l1 = l1 * c1 + sum1;

#pragma unroll
                for (int j = 0; j < 16; j++) {
                    o[j][0] *= c0; o[j][1] *= c0;
                    o[j][2] *= c1; o[j][3] *= c1;
                }

                // stage P (warp-private slab)
                {
                    __half* p0 = Ps + (w * 16 + g) * LDP;
                    __half* p1 = p0 + 8 * LDP;
#pragma unroll
                    for (int j = 0; j < 8; j++) {
                        *(uint32_t*)(p0 + j * 8 + 2 * t) = h2pack(s[j][0], s[j][1]);
                        *(uint32_t*)(p1 + j * 8 + 2 * t) = h2pack(s[j][2], s[j][3]);
                    }
                }
                __syncwarp();

                // O += P @ V (V transposed; this half's 64 key-columns)
#pragma unroll
                for (int k16 = 0; k16 < 4; k16++) {
                    const __half* pb = Ps + (w * 16 + g) * LDP + k16 * 16;
                    uint32_t a[4];
                    a[0] = *(const uint32_t*)(pb + 2 * t);
                    a[1] = *(const uint32_t*)(pb + 8 * LDP + 2 * t);
                    a[2] = *(const uint32_t*)(pb + 2 * t + 8);
                    a[3] = *(const uint32_t*)(pb + 8 * LDP + 2 * t + 8);
#pragma unroll
                    for (int j = 0; j < 16; j++) {
                        const __half* vb = Vcur + (j * 8 + g) * LDVT
                                           + h * 64 + k16 * 16;
                        uint32_t b[2];
                        b[0] = *(const uint32_t*)(vb + 2 * t);
                        b[1] = *(const uint32_t*)(vb + 2 * t + 8);
                        mma_f16(o[j], a, b);
                    }
                }
                __syncwarp();
            }
        }

        // normalize + store fp16
        float inv0 = 1.f / l0, inv1 = 1.f / l1;
#pragma unroll
        for (int j = 0; j < 16; j++) {
            __half* a0 = g_att + (size_t)row0g * HID + head * DH + j * 8 + 2 * t;
            __half* a1 = a0 + 8 * HID;
            *(uint32_t*)a0 = h2pack(o[j][0] * inv0, o[j][1] * inv0);
            *(uint32_t*)a1 = h2pack(o[j][2] * inv1, o[j][3] * inv1);
        }
        __syncthreads();   // protect smem before next item's loads
    }
}

// ---------------------------------------------------------------------------
extern "C" void kernel_launch(void* const* d_in, const int* in_sizes, int n_in,
                              void* d_out, int out_size)
{
    const float* x      = (const float*)d_in[0];
    const float* Wq     = (const float*)d_in[1];
    const float* bq     = (const float*)d_in[2];
    const float* Wk     = (const float*)d_in[3];
    const float* bk     = (const float*)d_in[4];
    const float* Wv     = (const float*)d_in[5];
    const float* bv     = (const float*)d_in[6];
    const float* Wo     = (const float*)d_in[7];
    const float* k_hist = (const float*)d_in[8];
    const float* v_hist = (const float*)d_in[9];
    const float* fcos   = (const float*)d_in[10];
    const float* fsin   = (const float*)d_in[11];
    float* out = (float*)d_out;

    cudaFuncSetAttribute(attn_kernel,
                         cudaFuncAttributeMaxDynamicSharedMemorySize, ATTN_SMEM);
    cudaFuncSetAttribute(gemm_qkv_kernel,
                         cudaFuncAttributeMaxDynamicSharedMemorySize, GEMM_SMEM);
    cudaFuncSetAttribute(gemm_wo_kernel,
                         cudaFuncAttributeMaxDynamicSharedMemorySize, GEMM_SMEM);

    // plain conversions + work-queue reset; tiled transposes
    cvt_kernel<<<1024, 256>>>(x, k_hist);
    trans_kernel<<<5888, 256>>>(Wq, Wk, Wv, Wo, v_hist);

    // fused QKV projection (fp16 mma)
    gemm_qkv_kernel<<<dim3(16, 16), 256, GEMM_SMEM>>>(bq, bk, bv);

    // RoPE
    rope_kernel<<<Q_LEN * 14, 64>>>(fcos, fsin);

    // attention (persistent, LPT queue, KTILE=128, halves, no spills)
    attn_kernel<<<148, 256, ATTN_SMEM>>>();

    // output projection (fp32 out)
    gemm_wo_kernel<<<dim3(HID / 128, Q_LEN / 128), 256, GEMM_SMEM>>>(out);
}

// round 13
// speedup vs baseline: 1.1814x; 1.1814x over previous
#include <cuda_runtime.h>
#include <cuda_fp16.h>
#include <math_constants.h>
#include <cstdint>

#define Q_LEN 2048
#define HIST  2048
#define KLEN  4096
#define NH    12
#define KVH   2
#define DH    128
#define HID   1536
#define KVDIM 256
#define GROUPS 6
#define NITEMS (NH * 16)

// Scratch (device globals, allocation-free)
__device__ __align__(16) __half g_q[Q_LEN * HID];      // [t][h*128+d]
__device__ __align__(16) __half g_k[KLEN * KVDIM];     // [key][kvh*128+d]
__device__ __align__(16) __half g_v[KVDIM * KLEN];     // TRANSPOSED [kvh*128+d][key]
__device__ __align__(16) __half g_att[Q_LEN * HID];    // [t][h*128+d]
__device__ __align__(16) __half g_x[Q_LEN * HID];      // [t][k]
__device__ __align__(16) __half g_wq[HID * HID];       // TRANSPOSED [n][k]
__device__ __align__(16) __half g_wk[KVDIM * HID];     // TRANSPOSED [n][k]
__device__ __align__(16) __half g_wv[KVDIM * HID];     // TRANSPOSED [n][k]
__device__ __align__(16) __half g_wo[HID * HID];       // TRANSPOSED [n][k]
__device__ unsigned int g_work;

// ---------------------------------------------------------------------------
// helpers
// ---------------------------------------------------------------------------
__device__ __forceinline__ uint32_t h2pack(float a, float b) {
    __half2 h = __floats2half2_rn(a, b);
    return *(uint32_t*)&h;
}

__device__ __forceinline__ void mma_f16(float d[4], const uint32_t a[4],
                                        const uint32_t b[2]) {
    asm volatile(
        "mma.sync.aligned.m16n8k16.row.col.f32.f16.f16.f32 "
        "{%0,%1,%2,%3}, {%4,%5,%6,%7}, {%8,%9}, {%0,%1,%2,%3};\n"
        : "+f"(d[0]), "+f"(d[1]), "+f"(d[2]), "+f"(d[3])
        : "r"(a[0]), "r"(a[1]), "r"(a[2]), "r"(a[3]), "r"(b[0]), "r"(b[1]));
}

__device__ __forceinline__ void cpa16(__half* dst, const __half* src) {
    uint32_t d = (uint32_t)__cvta_generic_to_shared(dst);
    asm volatile("cp.async.cg.shared.global [%0], [%1], 16;\n"
                 :: "r"(d), "l"(src));
}
#define CP_COMMIT() asm volatile("cp.async.commit_group;\n")
#define CP_WAIT(n)  asm volatile("cp.async.wait_group %0;\n" :: "n"(n))

// ---------------------------------------------------------------------------
// cvt: plain fp32 -> fp16 (x, k_hist); reset work counter
// ---------------------------------------------------------------------------
__global__ __launch_bounds__(256) void cvt_kernel(
    const float* __restrict__ x, const float* __restrict__ kh)
{
    if (blockIdx.x == 0 && threadIdx.x == 0) g_work = 0u;
    const int SX  = Q_LEN * HID / 2;
    const int SKH = HIST * KVDIM / 2;
    int stride = gridDim.x * blockDim.x;
    for (int i = blockIdx.x * blockDim.x + threadIdx.x; i < SX + SKH;
         i += stride) {
        if (i < SX) {
            float2 v = ((const float2*)x)[i];
            ((uint32_t*)g_x)[i] = h2pack(v.x, v.y);
        } else {
            int j = i - SX;
            float2 v = ((const float2*)kh)[j];
            ((uint32_t*)g_k)[j] = h2pack(v.x, v.y);
        }
    }
}

// ---------------------------------------------------------------------------
// Tiled transpose fp32->fp16 (coalesced both sides): weights and v_hist.
// 32x32 tiles, 256 threads. Tile jobs packed into blockIdx.x.
// ---------------------------------------------------------------------------
__global__ __launch_bounds__(256) void trans_kernel(
    const float* __restrict__ wq, const float* __restrict__ wk,
    const float* __restrict__ wv, const float* __restrict__ wo,
    const float* __restrict__ vh)
{
    __shared__ float tile[32][33];
    int b = blockIdx.x;
    const float* src; __half* dst;
    int inCols; size_t outStride; int tb;
    if (b < 2304)      { src = wq; dst = g_wq; inCols = 1536; outStride = 1536; tb = b; }
    else if (b < 2688) { src = wk; dst = g_wk; inCols = 256;  outStride = 1536; tb = b - 2304; }
    else if (b < 3072) { src = wv; dst = g_wv; inCols = 256;  outStride = 1536; tb = b - 2688; }
    else if (b < 5376) { src = wo; dst = g_wo; inCols = 1536; outStride = 1536; tb = b - 3072; }
    else               { src = vh; dst = g_v;  inCols = 256;  outStride = KLEN; tb = b - 5376; }
    int tilesPerRow = inCols >> 5;
    int row0 = (tb / tilesPerRow) << 5;
    int col0 = (tb % tilesPerRow) << 5;
    int tx = threadIdx.x & 31, ty = threadIdx.x >> 5;
#pragma unroll
    for (int l = 0; l < 4; l++) {
        int r = ty + 8 * l;
        tile[r][tx] = src[(size_t)(row0 + r) * inCols + col0 + tx];
    }
    __syncthreads();
#pragma unroll
    for (int l = 0; l < 4; l++) {
        int r = ty + 8 * l;   // output row = input col
        dst[(size_t)(col0 + r) * outStride + row0 + tx] =
            __float2half_rn(tile[tx][r]);
    }
}

// ---------------------------------------------------------------------------
// fp16 GEMM, cp.async 2-stage. C[128,128] = A[M,K] @ Bt[n][k] (+bias)
// modes: 0 = fp32 out, 1 = fp16 plain out, 2 = fp16 V-transposed out
// ---------------------------------------------------------------------------
#define LDA_G 40
#define LDB_G 40
#define GEMM_SMEM ((2 * 128 * LDA_G + 2 * 128 * LDB_G) * 2)

__device__ __forceinline__ void gemm_body_h(
    const __half* __restrict__ A, const __half* __restrict__ Bt,
    const float* __restrict__ bias, void* __restrict__ Cv,
    int row0, int col0, int K, int ldc, int mode)
{
    extern __shared__ __half smg[];
    __half* As = smg;
    __half* Bs = smg + 2 * 128 * LDA_G;

    const int tid  = threadIdx.x;
    const int w    = tid >> 5;
    const int lane = tid & 31;
    const int g    = lane >> 2;
    const int t    = lane & 3;
    const int wm   = w >> 2;
    const int wn   = w & 3;

    float acc[16][4];
#pragma unroll
    for (int i = 0; i < 16; i++)
#pragma unroll
        for (int j = 0; j < 4; j++) acc[i][j] = 0.f;

    auto load_stage = [&](int s, int k0) {
#pragma unroll
        for (int l = 0; l < 2; l++) {
            int i = tid + l * 256;
            int r = i >> 2, c = (i & 3) << 3;
            cpa16(As + (s * 128 + r) * LDA_G + c,
                  A + (size_t)(row0 + r) * K + k0 + c);
        }
#pragma unroll
        for (int l = 0; l < 2; l++) {
            int i = tid + l * 256;
            int r = i >> 2, c = (i & 3) << 3;
            cpa16(Bs + (s * 128 + r) * LDB_G + c,
                  Bt + (size_t)(col0 + r) * K + k0 + c);
        }
        CP_COMMIT();
    };

    load_stage(0, 0);
    const int KT = K / 32;
    for (int kt = 0; kt < KT; kt++) {
        if (kt + 1 < KT) { load_stage((kt + 1) & 1, (kt + 1) * 32); CP_WAIT(1); }
        else             { CP_WAIT(0); }
        __syncthreads();
        const __half* Ab = As + (kt & 1) * 128 * LDA_G;
        const __half* Bb = Bs + (kt & 1) * 128 * LDB_G;
#pragma unroll
        for (int k16 = 0; k16 < 32; k16 += 16) {
            uint32_t a[4][4];
#pragma unroll
            for (int mi = 0; mi < 4; mi++) {
                const __half* ab = Ab + (wm * 64 + mi * 16 + g) * LDA_G + k16;
                a[mi][0] = *(const uint32_t*)(ab + 2 * t);
                a[mi][1] = *(const uint32_t*)(ab + 8 * LDA_G + 2 * t);
                a[mi][2] = *(const uint32_t*)(ab + 2 * t + 8);
                a[mi][3] = *(const uint32_t*)(ab + 8 * LDA_G + 2 * t + 8);
            }
#pragma unroll
            for (int ni = 0; ni < 4; ni++) {
                const __half* bp = Bb + (wn * 32 + ni * 8 + g) * LDB_G + k16;
                uint32_t b[2];
                b[0] = *(const uint32_t*)(bp + 2 * t);
                b[1] = *(const uint32_t*)(bp + 2 * t + 8);
#pragma unroll
                for (int mi = 0; mi < 4; mi++)
                    mma_f16(acc[mi * 4 + ni], a[mi], b);
            }
        }
        __syncthreads();
    }

#pragma unroll
    for (int mi = 0; mi < 4; mi++)
#pragma unroll
        for (int ni = 0; ni < 4; ni++) {
            int col = col0 + wn * 32 + ni * 8 + 2 * t;
            float b0 = bias ? bias[col]     : 0.f;
            float b1 = bias ? bias[col + 1] : 0.f;
            int r0 = row0 + wm * 64 + mi * 16 + g;
            float v00 = acc[mi * 4 + ni][0] + b0;
            float v01 = acc[mi * 4 + ni][1] + b1;
            float v10 = acc[mi * 4 + ni][2] + b0;
            float v11 = acc[mi * 4 + ni][3] + b1;
            if (mode == 0) {
                float* C = (float*)Cv;
                *(float2*)(C + (size_t)r0 * ldc + col)       = make_float2(v00, v01);
                *(float2*)(C + (size_t)(r0 + 8) * ldc + col) = make_float2(v10, v11);
            } else if (mode == 1) {
                __half* C = (__half*)Cv;
                *(uint32_t*)(C + (size_t)r0 * ldc + col)       = h2pack(v00, v01);
                *(uint32_t*)(C + (size_t)(r0 + 8) * ldc + col) = h2pack(v10, v11);
            } else {
                __half* C = (__half*)Cv;
                int key = HIST + r0;
                C[(size_t)col * KLEN + key]           = __float2half_rn(v00);
                C[(size_t)(col + 1) * KLEN + key]     = __float2half_rn(v01);
                C[(size_t)col * KLEN + key + 8]       = __float2half_rn(v10);
                C[(size_t)(col + 1) * KLEN + key + 8] = __float2half_rn(v11);
            }
        }
}

// grid.x: 0..11 -> Wq, 12..13 -> Wk, 14..15 -> Wv
__global__ __launch_bounds__(256) void gemm_qkv_kernel(
    const float* __restrict__ bq, const float* __restrict__ bk,
    const float* __restrict__ bv)
{
    int bx   = blockIdx.x;
    int row0 = blockIdx.y * 128;
    if (bx < 12) {
        gemm_body_h(g_x, g_wq, bq, g_q, row0, bx * 128, HID, HID, 1);
    } else if (bx < 14) {
        gemm_body_h(g_x, g_wk, bk, g_k + (size_t)HIST * KVDIM, row0,
                    (bx - 12) * 128, HID, KVDIM, 1);
    } else {
        gemm_body_h(g_x, g_wv, bv, g_v, row0, (bx - 14) * 128, HID, 0, 2);
    }
}

__global__ __launch_bounds__(256) void gemm_wo_kernel(float* __restrict__ out)
{
    gemm_body_h(g_att, g_wo, nullptr, out, blockIdx.y * 128,
                blockIdx.x * 128, HID, HID, 0);
}

// ---------------------------------------------------------------------------
// RoPE, vectorized: 256-thread blocks, one warp per (t, head) job, half2 I/O.
// jobs: t * 14 + hh ; hh < 12 -> Q head, else new-K kv head.
// ---------------------------------------------------------------------------
__global__ __launch_bounds__(256) void rope_kernel(
    const float* __restrict__ fcos, const float* __restrict__ fsin)
{
    int job  = blockIdx.x * 8 + (threadIdx.x >> 5);
    int lane = threadIdx.x & 31;
    int t  = job / 14;
    int hh = job % 14;
    __half* base;
    if (hh < 12) base = g_q + (size_t)t * HID + hh * DH;
    else         base = g_k + (size_t)(HIST + t) * KVDIM + (hh - 12) * DH;
    float2 c2 = *(const float2*)(fcos + t * 64 + 2 * lane);
    float2 s2 = *(const float2*)(fsin + t * 64 + 2 * lane);
    __half2 a = *(__half2*)(base + 2 * lane);
    __half2 b = *(__half2*)(base + 64 + 2 * lane);
    float ax = __low2float(a), ay = __high2float(a);
    float bx = __low2float(b), by = __high2float(b);
    *(uint32_t*)(base + 2 * lane)      = h2pack(ax * c2.x - bx * s2.x,
                                                ay * c2.y - by * s2.y);
    *(uint32_t*)(base + 64 + 2 * lane) = h2pack(ax * s2.x + bx * c2.x,
                                                ay * s2.y + by * c2.y);
}

// ---------------------------------------------------------------------------
// Persistent flash attention, fp16 mma, KTILE=128 keys, ONE barrier per tile.
// (R9 configuration, verbatim — measured 175.5us)
// ---------------------------------------------------------------------------
#define KTILE 128
#define LDQ 136   // halves
#define LDK 136
#define LDVT 136
#define LDP 136
#define AQ_H (128 * LDQ)
#define AK_H (2 * 128 * LDK)
#define AV_H (2 * 128 * LDVT)
#define AP_H (128 * LDP)
#define AW_H (AQ_H + AK_H + AV_H + AP_H)
#define ATTN_SMEM (AW_H * 2 + 16)

__global__ __launch_bounds__(256) void attn_kernel()
{
    extern __shared__ __half smh[];
    __half* Qs = smh;
    __half* Ks = smh + AQ_H;
    __half* Vs = smh + AQ_H + AK_H;
    __half* Ps = smh + AQ_H + AK_H + AV_H;
    int* widx = (int*)(smh + AW_H);

    const int tid  = threadIdx.x;
    const int w    = tid >> 5;
    const int lane = tid & 31;
    const int g    = lane >> 2;
    const int t    = lane & 3;
    const float SC = 0.12751689932560563f;  // 1/sqrt(128) * log2(e)

    for (;;) {
        if (tid == 0) *widx = (int)atomicAdd(&g_work, 1u);
        __syncthreads();
        const int item = *widx;
        if (item >= NITEMS) break;
        const int qt   = 15 - item / NH;     // descending nkt (LPT)
        const int head = item % NH;
        const int q0   = qt * 128;
        const int kvh  = head / GROUPS;

        // Q tile (128 x 128 halves)
#pragma unroll
        for (int l = 0; l < 8; l++) {
            int i = tid + l * 256;
            int r = i >> 4, c = (i & 15) << 3;
            cpa16(Qs + r * LDQ + c, g_q + (size_t)(q0 + r) * HID + head * DH + c);
        }
        // K(0), V(0) into stage 0
#pragma unroll
        for (int l = 0; l < 8; l++) {
            int i = tid + l * 256;
            int r = i >> 4, c = (i & 15) << 3;
            cpa16(Ks + r * LDK + c, g_k + (size_t)r * KVDIM + kvh * DH + c);
        }
#pragma unroll
        for (int l = 0; l < 8; l++) {
            int i = tid + l * 256;
            int r = i >> 4, c = (i & 15) << 3;
            cpa16(Vs + r * LDVT + c, g_v + (size_t)(kvh * DH + r) * KLEN + c);
        }
        CP_COMMIT();
        CP_WAIT(0);
        __syncthreads();

        // capture Q fragments
        uint32_t qf[8][4];
#pragma unroll
        for (int k16 = 0; k16 < 8; k16++) {
            const __half* qb = Qs + (w * 16 + g) * LDQ + k16 * 16;
            qf[k16][0] = *(const uint32_t*)(qb + 2 * t);
            qf[k16][1] = *(const uint32_t*)(qb + 8 * LDQ + 2 * t);
            qf[k16][2] = *(const uint32_t*)(qb + 2 * t + 8);
            qf[k16][3] = *(const uint32_t*)(qb + 8 * LDQ + 2 * t + 8);
        }

        float o[16][4];
#pragma unroll
        for (int i = 0; i < 16; i++)
#pragma unroll
            for (int j = 0; j < 4; j++) o[i][j] = 0.f;
        float m0 = -1e30f, m1 = -1e30f, l0 = 0.f, l1 = 0.f;
        const int row0g = q0 + w * 16 + g;
        const int nkt = qt + 17;             // (q0 + 128 + HIST) / KTILE

        for (int kt = 0; kt < nkt; kt++) {
            const int kb = kt * KTILE;
            if (kt > 0) {
                CP_WAIT(0);          // K(kt), V(kt) arrived
                __syncthreads();     // ...and tile kt-1 fully consumed
            }
            // issue K(kt+1), V(kt+1) into the other buffers
            if (kt + 1 < nkt) {
                __half* Knx = Ks + ((kt + 1) & 1) * 128 * LDK;
                __half* Vnx = Vs + ((kt + 1) & 1) * 128 * LDVT;
#pragma unroll
                for (int l = 0; l < 8; l++) {
                    int i = tid + l * 256;
                    int r = i >> 4, c = (i & 15) << 3;
                    cpa16(Knx + r * LDK + c,
                          g_k + (size_t)(kb + KTILE + r) * KVDIM + kvh * DH + c);
                }
#pragma unroll
                for (int l = 0; l < 8; l++) {
                    int i = tid + l * 256;
                    int r = i >> 4, c = (i & 15) << 3;
                    cpa16(Vnx + r * LDVT + c,
                          g_v + (size_t)(kvh * DH + r) * KLEN + kb + KTILE + c);
                }
                CP_COMMIT();
            }

            const __half* Kcur = Ks + (kt & 1) * 128 * LDK;
            const __half* Vcur = Vs + (kt & 1) * 128 * LDVT;

            // S = Q K^T : 16 rows x 128 keys per warp
            float s[16][4];
#pragma unroll
            for (int j = 0; j < 16; j++)
#pragma unroll
                for (int e = 0; e < 4; e++) s[j][e] = 0.f;
#pragma unroll
            for (int k16 = 0; k16 < 8; k16++) {
#pragma unroll
                for (int j = 0; j < 16; j++) {
                    const __half* kp = Kcur + (j * 8 + g) * LDK + k16 * 16;
                    uint32_t b[2];
                    b[0] = *(const uint32_t*)(kp + 2 * t);
                    b[1] = *(const uint32_t*)(kp + 2 * t + 8);
                    mma_f16(s[j], qf[k16], b);
                }
            }

            // scale + causal mask (only the final tile is partial)
            if (kt == nkt - 1) {
#pragma unroll
                for (int j = 0; j < 16; j++) {
                    int colg = kb + j * 8 + 2 * t;
                    s[j][0] = (colg     <= row0g + HIST)     ? s[j][0] * SC : -1e30f;
                    s[j][1] = (colg + 1 <= row0g + HIST)     ? s[j][1] * SC : -1e30f;
                    s[j][2] = (colg     <= row0g + 8 + HIST) ? s[j][2] * SC : -1e30f;
                    s[j][3] = (colg + 1 <= row0g + 8 + HIST) ? s[j][3] * SC : -1e30f;
                }
            } else {
#pragma unroll
                for (int j = 0; j < 16; j++) {
                    s[j][0] *= SC; s[j][1] *= SC;
                    s[j][2] *= SC; s[j][3] *= SC;
                }
            }

            // online softmax (quad reduce)
            float mx0 = -1e30f, mx1 = -1e30f;
#pragma unroll
            for (int j = 0; j < 16; j++) {
                mx0 = fmaxf(mx0, fmaxf(s[j][0], s[j][1]));
                mx1 = fmaxf(mx1, fmaxf(s[j][2], s[j][3]));
            }
            mx0 = fmaxf(mx0, __shfl_xor_sync(0xffffffffu, mx0, 1));
            mx0 = fmaxf(mx0, __shfl_xor_sync(0xffffffffu, mx0, 2));
            mx1 = fmaxf(mx1, __shfl_xor_sync(0xffffffffu, mx1, 1));
            mx1 = fmaxf(mx1, __shfl_xor_sync(0xffffffffu, mx1, 2));
            float mn0 = fmaxf(m0, mx0), mn1 = fmaxf(m1, mx1);
            float c0 = exp2f(m0 - mn0), c1 = exp2f(m1 - mn1);
            m0 = mn0; m1 = mn1;
            float sum0 = 0.f, sum1 = 0.f;
#pragma unroll
            for (int j = 0; j < 16; j++) {
                s[j][0] = exp2f(s[j][0] - m0);
                s[j][1] = exp2f(s[j][1] - m0);
                s[j][2] = exp2f(s[j][2] - m1);
                s[j][3] = exp2f(s[j][3] - m1);
                sum0 += s[j][0] + s[j][1];
                sum1 += s[j][2] + s[j][3];
            }
            sum0 += __shfl_xor_sync(0xffffffffu, sum0, 1);
            sum0 += __shfl_xor_sync(0xffffffffu, sum0, 2);
            sum1 += __shfl_xor_sync(0xffffffffu, sum1, 1);
            sum1 += __shfl_xor_sync(0xffffffffu, sum1, 2);
            l0 = l0 * c0 + sum0;
            l1 = l1 * c1 + sum1;

#pragma unroll
            for (int j = 0; j < 16; j++) {
                o[j][0] *= c0; o[j][1] *= c0;
                o[j][2] *= c1; o[j][3] *= c1;
            }

            // stage P (warp-private slab)
            {
                __half* p0 = Ps + (w * 16 + g) * LDP;
                __half* p1 = p0 + 8 * LDP;
#pragma unroll
                for (int j = 0; j < 16; j++) {
                    *(uint32_t*)(p0 + j * 8 + 2 * t) = h2pack(s[j][0], s[j][1]);
                    *(uint32_t*)(p1 + j * 8 + 2 * t) = h2pack(s[j][2], s[j][3]);
                }
            }
            __syncwarp();

            // O += P @ V (V transposed)
#pragma unroll
            for (int k16 = 0; k16 < 8; k16++) {
                const __half* pb = Ps + (w * 16 + g) * LDP + k16 * 16;
                uint32_t a[4];
                a[0] = *(const uint32_t*)(pb + 2 * t);
                a[1] = *(const uint32_t*)(pb + 8 * LDP + 2 * t);
                a[2] = *(const uint32_t*)(pb + 2 * t + 8);
                a[3] = *(const uint32_t*)(pb + 8 * LDP + 2 * t + 8);
#pragma unroll
                for (int j = 0; j < 16; j++) {
                    const __half* vb = Vcur + (j * 8 + g) * LDVT + k16 * 16;
                    uint32_t b[2];
                    b[0] = *(const uint32_t*)(vb + 2 * t);
                    b[1] = *(const uint32_t*)(vb + 2 * t + 8);
                    mma_f16(o[j], a, b);
                }
            }
        }

        // normalize + store fp16
        float inv0 = 1.f / l0, inv1 = 1.f / l1;
#pragma unroll
        for (int j = 0; j < 16; j++) {
            __half* a0 = g_att + (size_t)row0g * HID + head * DH + j * 8 + 2 * t;
            __half* a1 = a0 + 8 * HID;
            *(uint32_t*)a0 = h2pack(o[j][0] * inv0, o[j][1] * inv0);
            *(uint32_t*)a1 = h2pack(o[j][2] * inv1, o[j][3] * inv1);
        }
        __syncthreads();   // protect smem before next item's loads
    }
}

// ---------------------------------------------------------------------------
extern "C" void kernel_launch(void* const* d_in, const int* in_sizes, int n_in,
                              void* d_out, int out_size)
{
    const float* x      = (const float*)d_in[0];
    const float* Wq     = (const float*)d_in[1];
    const float* bq     = (const float*)d_in[2];
    const float* Wk     = (const float*)d_in[3];
    const float* bk     = (const float*)d_in[4];
    const float* Wv     = (const float*)d_in[5];
    const float* bv     = (const float*)d_in[6];
    const float* Wo     = (const float*)d_in[7];
    const float* k_hist = (const float*)d_in[8];
    const float* v_hist = (const float*)d_in[9];
    const float* fcos   = (const float*)d_in[10];
    const float* fsin   = (const float*)d_in[11];
    float* out = (float*)d_out;

    cudaFuncSetAttribute(attn_kernel,
                         cudaFuncAttributeMaxDynamicSharedMemorySize, ATTN_SMEM);
    cudaFuncSetAttribute(gemm_qkv_kernel,
                         cudaFuncAttributeMaxDynamicSharedMemorySize, GEMM_SMEM);
    cudaFuncSetAttribute(gemm_wo_kernel,
                         cudaFuncAttributeMaxDynamicSharedMemorySize, GEMM_SMEM);

    // plain conversions + work-queue reset; tiled transposes
    cvt_kernel<<<1024, 256>>>(x, k_hist);
    trans_kernel<<<5888, 256>>>(Wq, Wk, Wv, Wo, v_hist);

    // fused QKV projection (fp16 mma)
    gemm_qkv_kernel<<<dim3(16, 16), 256, GEMM_SMEM>>>(bq, bk, bv);

    // RoPE (vectorized, warp per job)
    rope_kernel<<<Q_LEN * 14 / 8, 256>>>(fcos, fsin);

    // attention (persistent, LPT queue, KTILE=128, single barrier/tile)
    attn_kernel<<<148, 256, ATTN_SMEM>>>();

    // output projection (fp32 out)
    gemm_wo_kernel<<<dim3(HID / 128, Q_LEN / 128), 256, GEMM_SMEM>>>(out);
}

// round 15
// speedup vs baseline: 1.2383x; 1.0482x over previous
#include <cuda_runtime.h>
#include <cuda_fp16.h>
#include <math_constants.h>
#include <cstdint>

#define Q_LEN 2048
#define HIST  2048
#define KLEN  4096
#define NH    12
#define KVH   2
#define DH    128
#define HID   1536
#define KVDIM 256
#define GROUPS 6
#define NITEMS (NH * 16)

// Scratch (device globals, allocation-free)
__device__ __align__(16) __half g_q[Q_LEN * HID];      // [t][h*128+d]
__device__ __align__(16) __half g_k[KLEN * KVDIM];     // [key][kvh*128+d]
__device__ __align__(16) __half g_v[KVDIM * KLEN];     // TRANSPOSED [kvh*128+d][key]
__device__ __align__(16) __half g_att[Q_LEN * HID];    // [t][h*128+d]
__device__ __align__(16) __half g_x[Q_LEN * HID];      // [t][k]
__device__ __align__(16) __half g_wq[HID * HID];       // TRANSPOSED [n][k]
__device__ __align__(16) __half g_wk[KVDIM * HID];     // TRANSPOSED [n][k]
__device__ __align__(16) __half g_wv[KVDIM * HID];     // TRANSPOSED [n][k]
__device__ __align__(16) __half g_wo[HID * HID];       // TRANSPOSED [n][k]
__device__ unsigned int g_work;

// ---------------------------------------------------------------------------
// helpers
// ---------------------------------------------------------------------------
__device__ __forceinline__ uint32_t h2pack(float a, float b) {
    __half2 h = __floats2half2_rn(a, b);
    return *(uint32_t*)&h;
}

__device__ __forceinline__ void mma_f16(float d[4], const uint32_t a[4],
                                        const uint32_t b[2]) {
    asm volatile(
        "mma.sync.aligned.m16n8k16.row.col.f32.f16.f16.f32 "
        "{%0,%1,%2,%3}, {%4,%5,%6,%7}, {%8,%9}, {%0,%1,%2,%3};\n"
        : "+f"(d[0]), "+f"(d[1]), "+f"(d[2]), "+f"(d[3])
        : "r"(a[0]), "r"(a[1]), "r"(a[2]), "r"(a[3]), "r"(b[0]), "r"(b[1]));
}

__device__ __forceinline__ void cpa16(__half* dst, const __half* src) {
    uint32_t d = (uint32_t)__cvta_generic_to_shared(dst);
    asm volatile("cp.async.cg.shared.global [%0], [%1], 16;\n"
                 :: "r"(d), "l"(src));
}
#define CP_COMMIT() asm volatile("cp.async.commit_group;\n")
#define CP_WAIT(n)  asm volatile("cp.async.wait_group %0;\n" :: "n"(n))

// ---------------------------------------------------------------------------
// cvt: plain fp32 -> fp16 (x, k_hist); reset work counter
// ---------------------------------------------------------------------------
__global__ __launch_bounds__(256) void cvt_kernel(
    const float* __restrict__ x, const float* __restrict__ kh)
{
    if (blockIdx.x == 0 && threadIdx.x == 0) g_work = 0u;
    const int SX  = Q_LEN * HID / 2;
    const int SKH = HIST * KVDIM / 2;
    int stride = gridDim.x * blockDim.x;
    for (int i = blockIdx.x * blockDim.x + threadIdx.x; i < SX + SKH;
         i += stride) {
        if (i < SX) {
            float2 v = ((const float2*)x)[i];
            ((uint32_t*)g_x)[i] = h2pack(v.x, v.y);
        } else {
            int j = i - SX;
            float2 v = ((const float2*)kh)[j];
            ((uint32_t*)g_k)[j] = h2pack(v.x, v.y);
        }
    }
}

// ---------------------------------------------------------------------------
// Tiled transpose fp32->fp16 (coalesced both sides): weights and v_hist.
// ---------------------------------------------------------------------------
__global__ __launch_bounds__(256) void trans_kernel(
    const float* __restrict__ wq, const float* __restrict__ wk,
    const float* __restrict__ wv, const float* __restrict__ wo,
    const float* __restrict__ vh)
{
    __shared__ float tile[32][33];
    int b = blockIdx.x;
    const float* src; __half* dst;
    int inCols; size_t outStride; int tb;
    if (b < 2304)      { src = wq; dst = g_wq; inCols = 1536; outStride = 1536; tb = b; }
    else if (b < 2688) { src = wk; dst = g_wk; inCols = 256;  outStride = 1536; tb = b - 2304; }
    else if (b < 3072) { src = wv; dst = g_wv; inCols = 256;  outStride = 1536; tb = b - 2688; }
    else if (b < 5376) { src = wo; dst = g_wo; inCols = 1536; outStride = 1536; tb = b - 3072; }
    else               { src = vh; dst = g_v;  inCols = 256;  outStride = KLEN; tb = b - 5376; }
    int tilesPerRow = inCols >> 5;
    int row0 = (tb / tilesPerRow) << 5;
    int col0 = (tb % tilesPerRow) << 5;
    int tx = threadIdx.x & 31, ty = threadIdx.x >> 5;
#pragma unroll
    for (int l = 0; l < 4; l++) {
        int r = ty + 8 * l;
        tile[r][tx] = src[(size_t)(row0 + r) * inCols + col0 + tx];
    }
    __syncthreads();
#pragma unroll
    for (int l = 0; l < 4; l++) {
        int r = ty + 8 * l;   // output row = input col
        dst[(size_t)(col0 + r) * outStride + row0 + tx] =
            __float2half_rn(tile[tx][r]);
    }
}

// ---------------------------------------------------------------------------
// fp16 GEMM, cp.async 2-stage. C[128,128] = A[M,K] @ Bt[n][k] (+bias)
// modes: 0 = fp32 out, 1 = fp16 plain out, 2 = fp16 V-transposed out
// ---------------------------------------------------------------------------
#define LDA_G 40
#define LDB_G 40
#define GEMM_SMEM ((2 * 128 * LDA_G + 2 * 128 * LDB_G) * 2)

__device__ __forceinline__ void gemm_body_h(
    const __half* __restrict__ A, const __half* __restrict__ Bt,
    const float* __restrict__ bias, void* __restrict__ Cv,
    int row0, int col0, int K, int ldc, int mode)
{
    extern __shared__ __half smg[];
    __half* As = smg;
    __half* Bs = smg + 2 * 128 * LDA_G;

    const int tid  = threadIdx.x;
    const int w    = tid >> 5;
    const int lane = tid & 31;
    const int g    = lane >> 2;
    const int t    = lane & 3;
    const int wm   = w >> 2;
    const int wn   = w & 3;

    float acc[16][4];
#pragma unroll
    for (int i = 0; i < 16; i++)
#pragma unroll
        for (int j = 0; j < 4; j++) acc[i][j] = 0.f;

    auto load_stage = [&](int s, int k0) {
#pragma unroll
        for (int l = 0; l < 2; l++) {
            int i = tid + l * 256;
            int r = i >> 2, c = (i & 3) << 3;
            cpa16(As + (s * 128 + r) * LDA_G + c,
                  A + (size_t)(row0 + r) * K + k0 + c);
        }
#pragma unroll
        for (int l = 0; l < 2; l++) {
            int i = tid + l * 256;
            int r = i >> 2, c = (i & 3) << 3;
            cpa16(Bs + (s * 128 + r) * LDB_G + c,
                  Bt + (size_t)(col0 + r) * K + k0 + c);
        }
        CP_COMMIT();
    };

    load_stage(0, 0);
    const int KT = K / 32;
    for (int kt = 0; kt < KT; kt++) {
        if (kt + 1 < KT) { load_stage((kt + 1) & 1, (kt + 1) * 32); CP_WAIT(1); }
        else             { CP_WAIT(0); }
        __syncthreads();
        const __half* Ab = As + (kt & 1) * 128 * LDA_G;
        const __half* Bb = Bs + (kt & 1) * 128 * LDB_G;
#pragma unroll
        for (int k16 = 0; k16 < 32; k16 += 16) {
            uint32_t a[4][4];
#pragma unroll
            for (int mi = 0; mi < 4; mi++) {
                const __half* ab = Ab + (wm * 64 + mi * 16 + g) * LDA_G + k16;
                a[mi][0] = *(const uint32_t*)(ab + 2 * t);
                a[mi][1] = *(const uint32_t*)(ab + 8 * LDA_G + 2 * t);
                a[mi][2] = *(const uint32_t*)(ab + 2 * t + 8);
                a[mi][3] = *(const uint32_t*)(ab + 8 * LDA_G + 2 * t + 8);
            }
#pragma unroll
            for (int ni = 0; ni < 4; ni++) {
                const __half* bp = Bb + (wn * 32 + ni * 8 + g) * LDB_G + k16;
                uint32_t b[2];
                b[0] = *(const uint32_t*)(bp + 2 * t);
                b[1] = *(const uint32_t*)(bp + 2 * t + 8);
#pragma unroll
                for (int mi = 0; mi < 4; mi++)
                    mma_f16(acc[mi * 4 + ni], a[mi], b);
            }
        }
        __syncthreads();
    }

#pragma unroll
    for (int mi = 0; mi < 4; mi++)
#pragma unroll
        for (int ni = 0; ni < 4; ni++) {
            int col = col0 + wn * 32 + ni * 8 + 2 * t;
            float b0 = bias ? bias[col]     : 0.f;
            float b1 = bias ? bias[col + 1] : 0.f;
            int r0 = row0 + wm * 64 + mi * 16 + g;
            float v00 = acc[mi * 4 + ni][0] + b0;
            float v01 = acc[mi * 4 + ni][1] + b1;
            float v10 = acc[mi * 4 + ni][2] + b0;
            float v11 = acc[mi * 4 + ni][3] + b1;
            if (mode == 0) {
                float* C = (float*)Cv;
                *(float2*)(C + (size_t)r0 * ldc + col)       = make_float2(v00, v01);
                *(float2*)(C + (size_t)(r0 + 8) * ldc + col) = make_float2(v10, v11);
            } else if (mode == 1) {
                __half* C = (__half*)Cv;
                *(uint32_t*)(C + (size_t)r0 * ldc + col)       = h2pack(v00, v01);
                *(uint32_t*)(C + (size_t)(r0 + 8) * ldc + col) = h2pack(v10, v11);
            } else {
                __half* C = (__half*)Cv;
                int key = HIST + r0;
                C[(size_t)col * KLEN + key]           = __float2half_rn(v00);
                C[(size_t)(col + 1) * KLEN + key]     = __float2half_rn(v01);
                C[(size_t)col * KLEN + key + 8]       = __float2half_rn(v10);
                C[(size_t)(col + 1) * KLEN + key + 8] = __float2half_rn(v11);
            }
        }
}

// grid.x: 0..11 -> Wq, 12..13 -> Wk, 14..15 -> Wv
__global__ __launch_bounds__(256) void gemm_qkv_kernel(
    const float* __restrict__ bq, const float* __restrict__ bk,
    const float* __restrict__ bv)
{
    int bx   = blockIdx.x;
    int row0 = blockIdx.y * 128;
    if (bx < 12) {
        gemm_body_h(g_x, g_wq, bq, g_q, row0, bx * 128, HID, HID, 1);
    } else if (bx < 14) {
        gemm_body_h(g_x, g_wk, bk, g_k + (size_t)HIST * KVDIM, row0,
                    (bx - 12) * 128, HID, KVDIM, 1);
    } else {
        gemm_body_h(g_x, g_wv, bv, g_v, row0, (bx - 14) * 128, HID, 0, 2);
    }
}

__global__ __launch_bounds__(256) void gemm_wo_kernel(float* __restrict__ out)
{
    gemm_body_h(g_att, g_wo, nullptr, out, blockIdx.y * 128,
                blockIdx.x * 128, HID, HID, 0);
}

// ---------------------------------------------------------------------------
// RoPE, vectorized: 256-thread blocks, one warp per (t, head) job, half2 I/O.
// ---------------------------------------------------------------------------
__global__ __launch_bounds__(256) void rope_kernel(
    const float* __restrict__ fcos, const float* __restrict__ fsin)
{
    int job  = blockIdx.x * 8 + (threadIdx.x >> 5);
    int lane = threadIdx.x & 31;
    int t  = job / 14;
    int hh = job % 14;
    __half* base;
    if (hh < 12) base = g_q + (size_t)t * HID + hh * DH;
    else         base = g_k + (size_t)(HIST + t) * KVDIM + (hh - 12) * DH;
    float2 c2 = *(const float2*)(fcos + t * 64 + 2 * lane);
    float2 s2 = *(const float2*)(fsin + t * 64 + 2 * lane);
    __half2 a = *(__half2*)(base + 2 * lane);
    __half2 b = *(__half2*)(base + 64 + 2 * lane);
    float ax = __low2float(a), ay = __high2float(a);
    float bx = __low2float(b), by = __high2float(b);
    *(uint32_t*)(base + 2 * lane)      = h2pack(ax * c2.x - bx * s2.x,
                                                ay * c2.y - by * s2.y);
    *(uint32_t*)(base + 64 + 2 * lane) = h2pack(ax * s2.x + bx * c2.x,
                                                ay * s2.y + by * c2.y);
}

// ---------------------------------------------------------------------------
// Persistent flash attention, fp16 mma, KTILE=128, one barrier per tile.
// P lives in registers (S-accumulator == PV A-fragment identity);
// row-sum l computed by tensor core via ones-rows (128..135) of V smem.
// ---------------------------------------------------------------------------
#define KTILE 128
#define LDQ 136   // halves
#define LDK 136
#define LDVT 136
#define VROWS 136  // 128 data rows + 8 ones rows
#define AQ_H (128 * LDQ)
#define AK_H (2 * 128 * LDK)
#define AV_H (2 * VROWS * LDVT)
#define AW_H (AQ_H + AK_H + AV_H)
#define ATTN_SMEM (AW_H * 2 + 16)

__global__ __launch_bounds__(256) void attn_kernel()
{
    extern __shared__ __half smh[];
    __half* Qs = smh;
    __half* Ks = smh + AQ_H;
    __half* Vs = smh + AQ_H + AK_H;
    int* widx = (int*)(smh + AW_H);

    const int tid  = threadIdx.x;
    const int w    = tid >> 5;
    const int lane = tid & 31;
    const int g    = lane >> 2;
    const int t    = lane & 3;
    const float SC = 0.12751689932560563f;  // 1/sqrt(128) * log2(e)

    // ones rows (d = 128..135) of both V stage buffers; cp.async never
    // touches rows >= 128, so these persist for the whole kernel.
    for (int i = tid; i < 2 * 8 * LDVT; i += 256) {
        int buf = i / (8 * LDVT);
        int rem = i % (8 * LDVT);
        Vs[buf * VROWS * LDVT + (128 + rem / LDVT) * LDVT + (rem % LDVT)] =
            __float2half(1.f);
    }

    for (;;) {
        if (tid == 0) *widx = (int)atomicAdd(&g_work, 1u);
        __syncthreads();
        const int item = *widx;
        if (item >= NITEMS) break;
        const int qt   = 15 - item / NH;     // descending nkt (LPT)
        const int head = item % NH;
        const int q0   = qt * 128;
        const int kvh  = head / GROUPS;

        // Q tile (128 x 128 halves)
#pragma unroll
        for (int l = 0; l < 8; l++) {
            int i = tid + l * 256;
            int r = i >> 4, c = (i & 15) << 3;
            cpa16(Qs + r * LDQ + c, g_q + (size_t)(q0 + r) * HID + head * DH + c);
        }
        // K(0), V(0) into stage 0
#pragma unroll
        for (int l = 0; l < 8; l++) {
            int i = tid + l * 256;
            int r = i >> 4, c = (i & 15) << 3;
            cpa16(Ks + r * LDK + c, g_k + (size_t)r * KVDIM + kvh * DH + c);
        }
#pragma unroll
        for (int l = 0; l < 8; l++) {
            int i = tid + l * 256;
            int r = i >> 4, c = (i & 15) << 3;
            cpa16(Vs + r * LDVT + c, g_v + (size_t)(kvh * DH + r) * KLEN + c);
        }
        CP_COMMIT();
        CP_WAIT(0);
        __syncthreads();

        // capture Q fragments
        uint32_t qf[8][4];
#pragma unroll
        for (int k16 = 0; k16 < 8; k16++) {
            const __half* qb = Qs + (w * 16 + g) * LDQ + k16 * 16;
            qf[k16][0] = *(const uint32_t*)(qb + 2 * t);
            qf[k16][1] = *(const uint32_t*)(qb + 8 * LDQ + 2 * t);
            qf[k16][2] = *(const uint32_t*)(qb + 2 * t + 8);
            qf[k16][3] = *(const uint32_t*)(qb + 8 * LDQ + 2 * t + 8);
        }

        float o[16][4];
#pragma unroll
        for (int i = 0; i < 16; i++)
#pragma unroll
            for (int j = 0; j < 4; j++) o[i][j] = 0.f;
        float ol[4] = {0.f, 0.f, 0.f, 0.f};   // tensor-core row-sum (l)
        float m0 = -1e30f, m1 = -1e30f;
        const int row0g = q0 + w * 16 + g;
        const int nkt = qt + 17;             // (q0 + 128 + HIST) / KTILE

        for (int kt = 0; kt < nkt; kt++) {
            const int kb = kt * KTILE;
            if (kt > 0) {
                CP_WAIT(0);          // K(kt), V(kt) arrived
                __syncthreads();     // ...and tile kt-1 fully consumed
            }
            // issue K(kt+1), V(kt+1) into the other buffers
            if (kt + 1 < nkt) {
                __half* Knx = Ks + ((kt + 1) & 1) * 128 * LDK;
                __half* Vnx = Vs + ((kt + 1) & 1) * VROWS * LDVT;
#pragma unroll
                for (int l = 0; l < 8; l++) {
                    int i = tid + l * 256;
                    int r = i >> 4, c = (i & 15) << 3;
                    cpa16(Knx + r * LDK + c,
                          g_k + (size_t)(kb + KTILE + r) * KVDIM + kvh * DH + c);
                }
#pragma unroll
                for (int l = 0; l < 8; l++) {
                    int i = tid + l * 256;
                    int r = i >> 4, c = (i & 15) << 3;
                    cpa16(Vnx + r * LDVT + c,
                          g_v + (size_t)(kvh * DH + r) * KLEN + kb + KTILE + c);
                }
                CP_COMMIT();
            }

            const __half* Kcur = Ks + (kt & 1) * 128 * LDK;
            const __half* Vcur = Vs + (kt & 1) * VROWS * LDVT;

            // S = Q K^T : 16 rows x 128 keys per warp
            float s[16][4];
#pragma unroll
            for (int j = 0; j < 16; j++)
#pragma unroll
                for (int e = 0; e < 4; e++) s[j][e] = 0.f;
#pragma unroll
            for (int k16 = 0; k16 < 8; k16++) {
#pragma unroll
                for (int j = 0; j < 16; j++) {
                    const __half* kp = Kcur + (j * 8 + g) * LDK + k16 * 16;
                    uint32_t b[2];
                    b[0] = *(const uint32_t*)(kp + 2 * t);
                    b[1] = *(const uint32_t*)(kp + 2 * t + 8);
                    mma_f16(s[j], qf[k16], b);
                }
            }

            // scale + causal mask (only the final tile is partial)
            if (kt == nkt - 1) {
#pragma unroll
                for (int j = 0; j < 16; j++) {
                    int colg = kb + j * 8 + 2 * t;
                    s[j][0] = (colg     <= row0g + HIST)     ? s[j][0] * SC : -1e30f;
                    s[j][1] = (colg + 1 <= row0g + HIST)     ? s[j][1] * SC : -1e30f;
                    s[j][2] = (colg     <= row0g + 8 + HIST) ? s[j][2] * SC : -1e30f;
                    s[j][3] = (colg + 1 <= row0g + 8 + HIST) ? s[j][3] * SC : -1e30f;
                }
            } else {
#pragma unroll
                for (int j = 0; j < 16; j++) {
                    s[j][0] *= SC; s[j][1] *= SC;
                    s[j][2] *= SC; s[j][3] *= SC;
                }
            }

            // online softmax: row max (quad reduce)
            float mx0 = -1e30f, mx1 = -1e30f;
#pragma unroll
            for (int j = 0; j < 16; j++) {
                mx0 = fmaxf(mx0, fmaxf(s[j][0], s[j][1]));
                mx1 = fmaxf(mx1, fmaxf(s[j][2], s[j][3]));
            }
            mx0 = fmaxf(mx0, __shfl_xor_sync(0xffffffffu, mx0, 1));
            mx0 = fmaxf(mx0, __shfl_xor_sync(0xffffffffu, mx0, 2));
            mx1 = fmaxf(mx1, __shfl_xor_sync(0xffffffffu, mx1, 1));
            mx1 = fmaxf(mx1, __shfl_xor_sync(0xffffffffu, mx1, 2));
            float mn0 = fmaxf(m0, mx0), mn1 = fmaxf(m1, mx1);
            float c0 = exp2f(m0 - mn0), c1 = exp2f(m1 - mn1);
            m0 = mn0; m1 = mn1;

            // exp + pack directly into PV A-fragments (P stays in registers)
            uint32_t pa[8][4];
#pragma unroll
            for (int j2 = 0; j2 < 8; j2++) {
                float e00 = exp2f(s[2 * j2][0] - m0);
                float e01 = exp2f(s[2 * j2][1] - m0);
                float e02 = exp2f(s[2 * j2][2] - m1);
                float e03 = exp2f(s[2 * j2][3] - m1);
                float e10 = exp2f(s[2 * j2 + 1][0] - m0);
                float e11 = exp2f(s[2 * j2 + 1][1] - m0);
                float e12 = exp2f(s[2 * j2 + 1][2] - m1);
                float e13 = exp2f(s[2 * j2 + 1][3] - m1);
                pa[j2][0] = h2pack(e00, e01);
                pa[j2][1] = h2pack(e02, e03);
                pa[j2][2] = h2pack(e10, e11);
                pa[j2][3] = h2pack(e12, e13);
            }

            // rescale O and l accumulators
#pragma unroll
            for (int j = 0; j < 16; j++) {
                o[j][0] *= c0; o[j][1] *= c0;
                o[j][2] *= c1; o[j][3] *= c1;
            }
            ol[0] *= c0; ol[1] *= c0; ol[2] *= c1; ol[3] *= c1;

            // O += P @ V (V transposed); j = 16 is the ones-rows -> l
#pragma unroll
            for (int k16 = 0; k16 < 8; k16++) {
#pragma unroll
                for (int j = 0; j < 16; j++) {
                    const __half* vb = Vcur + (j * 8 + g) * LDVT + k16 * 16;
                    uint32_t b[2];
                    b[0] = *(const uint32_t*)(vb + 2 * t);
                    b[1] = *(const uint32_t*)(vb + 2 * t + 8);
                    mma_f16(o[j], pa[k16], b);
                }
                {
                    const __half* vb = Vcur + (128 + g) * LDVT + k16 * 16;
                    uint32_t b[2];
                    b[0] = *(const uint32_t*)(vb + 2 * t);
                    b[1] = *(const uint32_t*)(vb + 2 * t + 8);
                    mma_f16(ol, pa[k16], b);
                }
            }
        }

        // normalize + store fp16 (l from tensor-core ones-column)
        float inv0 = 1.f / ol[0], inv1 = 1.f / ol[2];
#pragma unroll
        for (int j = 0; j < 16; j++) {
            __half* a0 = g_att + (size_t)row0g * HID + head * DH + j * 8 + 2 * t;
            __half* a1 = a0 + 8 * HID;
            *(uint32_t*)a0 = h2pack(o[j][0] * inv0, o[j][1] * inv0);
            *(uint32_t*)a1 = h2pack(o[j][2] * inv1, o[j][3] * inv1);
        }
        __syncthreads();   // protect smem before next item's loads
    }
}

// ---------------------------------------------------------------------------
extern "C" void kernel_launch(void* const* d_in, const int* in_sizes, int n_in,
                              void* d_out, int out_size)
{
    const float* x      = (const float*)d_in[0];
    const float* Wq     = (const float*)d_in[1];
    const float* bq     = (const float*)d_in[2];
    const float* Wk     = (const float*)d_in[3];
    const float* bk     = (const float*)d_in[4];
    const float* Wv     = (const float*)d_in[5];
    const float* bv     = (const float*)d_in[6];
    const float* Wo     = (const float*)d_in[7];
    const float* k_hist = (const float*)d_in[8];
    const float* v_hist = (const float*)d_in[9];
    const float* fcos   = (const float*)d_in[10];
    const float* fsin   = (const float*)d_in[11];
    float* out = (float*)d_out;

    cudaFuncSetAttribute(attn_kernel,
                         cudaFuncAttributeMaxDynamicSharedMemorySize, ATTN_SMEM);
    cudaFuncSetAttribute(gemm_qkv_kernel,
                         cudaFuncAttributeMaxDynamicSharedMemorySize, GEMM_SMEM);
    cudaFuncSetAttribute(gemm_wo_kernel,
                         cudaFuncAttributeMaxDynamicSharedMemorySize, GEMM_SMEM);

    // plain conversions + work-queue reset; tiled transposes
    cvt_kernel<<<1024, 256>>>(x, k_hist);
    trans_kernel<<<5888, 256>>>(Wq, Wk, Wv, Wo, v_hist);

    // fused QKV projection (fp16 mma)
    gemm_qkv_kernel<<<dim3(16, 16), 256, GEMM_SMEM>>>(bq, bk, bv);

    // RoPE (vectorized, warp per job)
    rope_kernel<<<Q_LEN * 14 / 8, 256>>>(fcos, fsin);

    // attention (persistent, LPT queue, KTILE=128, P-in-registers)
    attn_kernel<<<148, 256, ATTN_SMEM>>>();

    // output projection (fp32 out)
    gemm_wo_kernel<<<dim3(HID / 128, Q_LEN / 128), 256, GEMM_SMEM>>>(out);
}